// round 5
// baseline (speedup 1.0000x reference)
#include <cuda_runtime.h>

#define MAXD 365
#define HSZ  512          // padded histogram, mask 511 (crash-proof, clamp-free)
#define NTHR 512
#define NBLK 456          // 3 blocks/SM * 152 SMs

__device__ float    g_S[MAXD];      // sum exp(clip(y)) per bucket
__device__ unsigned g_M[MAXD];      // event count per bucket
__device__ float    g_sum_ey;       // sum e_i * y_i
__device__ float    g_sum_y;        // sum y_i
__device__ unsigned g_done;

__device__ __forceinline__ void proc4(const float4& y, const int4& d, const int4& e,
                                      float* sS, unsigned* sM, float& ey, float& sy)
{
    #pragma unroll
    for (int k = 0; k < 4; k++) {
        float yy = (&y.x)[k];
        int   dd = (&d.x)[k] & (HSZ - 1);
        int   ec = (&e.x)[k];
        float x  = fminf(fmaxf(yy, -20.f), 20.f);
        float ex = __expf(x);
        atomicAdd(&sS[dd], ex);
        if (ec) {
            atomicAdd(&sM[dd], 1u);
            ey += yy;
        }
        sy += yy;
    }
}

__global__ void __launch_bounds__(NTHR, 3)
cox_fused_kernel(const float* __restrict__ pred,
                 const int*   __restrict__ dur,
                 const int*   __restrict__ ev,
                 float* __restrict__ out,
                 int n)
{
    __shared__ float    sS[HSZ];     // reused as suffix-scan array in finalize
    __shared__ unsigned sM[HSZ];     // reused as redN in finalize
    __shared__ float    sLg[HSZ];    // log R LUT (finalize)
    __shared__ float    redM[HSZ];   // reduction scratch (finalize)
    __shared__ float    wA[NTHR / 32], wB[NTHR / 32];
    __shared__ unsigned sIsLast;

    int t = threadIdx.x;
    for (int i = t; i < HSZ; i += NTHR) { sS[i] = 0.f; sM[i] = 0u; }
    __syncthreads();

    float ey = 0.f, sy = 0.f;

    const int nv     = n >> 2;
    const int stride = NBLK * NTHR;
    const float4* p4 = (const float4*)pred;
    const int4*   d4 = (const int4*)dur;
    const int4*   e4 = (const int4*)ev;

    for (int i = blockIdx.x * NTHR + t; i < nv; i += 2 * stride) {
        // batch all loads first (MLP up to 6 LDG.128)
        float4 yA = __ldcs(&p4[i]);
        int4   dA = __ldcs(&d4[i]);
        int4   eA = __ldcs(&e4[i]);
        int j = i + stride;
        bool hb = j < nv;
        float4 yB; int4 dB, eB;
        if (hb) { yB = __ldcs(&p4[j]); dB = __ldcs(&d4[j]); eB = __ldcs(&e4[j]); }

        proc4(yA, dA, eA, sS, sM, ey, sy);
        if (hb) proc4(yB, dB, eB, sS, sM, ey, sy);
    }
    // scalar tail (N%4 != 0 safety)
    for (int i = (nv << 2) + blockIdx.x * NTHR + t; i < n; i += stride) {
        float yy = pred[i];
        int   dd = dur[i] & (HSZ - 1);
        int   ec = ev[i];
        float x  = fminf(fmaxf(yy, -20.f), 20.f);
        atomicAdd(&sS[dd], __expf(x));
        if (ec) { atomicAdd(&sM[dd], 1u); ey += yy; }
        sy += yy;
    }

    // block reduce ey, sy -> global
    int lane = t & 31, wid = t >> 5;
    #pragma unroll
    for (int o = 16; o; o >>= 1) {
        ey += __shfl_down_sync(0xffffffffu, ey, o);
        sy += __shfl_down_sync(0xffffffffu, sy, o);
    }
    if (lane == 0) { wA[wid] = ey; wB[wid] = sy; }
    __syncthreads();
    if (t == 0) {
        float a = 0.f, b = 0.f;
        #pragma unroll
        for (int w = 0; w < NTHR / 32; w++) { a += wA[w]; b += wB[w]; }
        atomicAdd(&g_sum_ey, a);
        atomicAdd(&g_sum_y,  b);
    }

    // flush histograms (skip empty buckets)
    for (int i = t; i < MAXD; i += NTHR) {
        float s = sS[i];
        if (s != 0.f) atomicAdd(&g_S[i], s);
        unsigned m = sM[i];
        if (m)        atomicAdd(&g_M[i], m);
    }

    // ---- last-block finalize ----
    __threadfence();
    if (t == 0) {
        unsigned ticket = atomicAdd(&g_done, 1u);
        sIsLast = (ticket == (unsigned)(gridDim.x - 1)) ? 1u : 0u;
    }
    __syncthreads();
    if (!sIsLast) return;

    float    s = (t < MAXD) ? __ldcg(&g_S[t]) : 0.f;
    unsigned m = (t < MAXD) ? __ldcg(&g_M[t]) : 0u;
    __syncthreads();          // safe to reuse sS/sM now
    sS[t] = s;
    __syncthreads();

    // Hillis-Steele inclusive suffix scan: sS[t] = sum_{j>=t} S[j]
    #pragma unroll
    for (int off = 1; off < HSZ; off <<= 1) {
        float v = (t + off < HSZ) ? sS[t + off] : 0.f;
        __syncthreads();
        sS[t] += v;
        __syncthreads();
    }

    float R  = fmaxf(sS[t], 1e-12f);
    float lg = logf(R);
    sLg[t]  = (t < MAXD) ? lg : 0.f;
    redM[t] = (float)m * ((t < MAXD) ? lg : 0.f);
    sM[t]   = m;
    __syncthreads();

    #pragma unroll
    for (int off = HSZ / 2; off; off >>= 1) {
        if (t < off) {
            redM[t] += redM[t + off];
            sM[t]   += sM[t + off];
        }
        __syncthreads();
    }

    unsigned nev = sM[0];

    if (nev > 0u) {
        if (t == 0) {
            float total_ll = __ldcg(&g_sum_ey) - redM[0];
            out[0] = -total_ll / fmaxf((float)nev, 1.f);
        }
    } else {
        // dead-in-practice corner: e.sum()==0 -> e := 1e-8 everywhere.
        // Need sum_i log R[dur_i]; re-scan durations with this one block.
        float slr = 0.f;
        for (int i = t; i < n; i += NTHR)
            slr += sLg[dur[i] & (HSZ - 1)];
        #pragma unroll
        for (int o = 16; o; o >>= 1)
            slr += __shfl_down_sync(0xffffffffu, slr, o);
        if (lane == 0) wA[wid] = slr;
        __syncthreads();
        if (t == 0) {
            float tot = 0.f;
            #pragma unroll
            for (int w = 0; w < NTHR / 32; w++) tot += wA[w];
            float total_ll = 1e-8f * (__ldcg(&g_sum_y) - tot);
            float n_events = fmaxf(1e-8f * (float)n, 1.f);
            out[0] = -total_ll / n_events;
        }
    }

    // re-zero globals for next graph replay
    __syncthreads();
    for (int i = t; i < MAXD; i += NTHR) { g_S[i] = 0.f; g_M[i] = 0u; }
    if (t == 0) { g_sum_ey = 0.f; g_sum_y = 0.f; g_done = 0u; }
}

extern "C" void kernel_launch(void* const* d_in, const int* in_sizes, int n_in,
                              void* d_out, int out_size)
{
    const float* pred = (const float*)d_in[0];
    const int*   dur  = (const int*)d_in[1];
    const int*   ev   = (const int*)d_in[2];
    int n = in_sizes[0];

    cox_fused_kernel<<<NBLK, NTHR>>>(pred, dur, ev, (float*)d_out, n);
}

// round 6
// speedup vs baseline: 1.2246x; 1.2246x over previous
#include <cuda_runtime.h>

#define MAXD 365
#define HSZ  512          // padded LUT/hist, mask 511 (clamp-free, crash-proof)
#define NTHR 512
#define NBLK 296          // 2 blocks/SM * 148 SMs -> all resident (spin barrier safe)
#define NWRP (NTHR / 32)

__device__ float    g_S[MAXD];      // sum exp(clip(y)) per bucket
__device__ float    g_slr_e;        // sum e_i * logR[dur_i]
__device__ float    g_slr_all;      // sum   logR[dur_i]       (no-events corner)
__device__ float    g_sey;          // sum e_i * y_i
__device__ float    g_sy;           // sum y_i                 (no-events corner)
__device__ unsigned g_nev;          // total events
__device__ unsigned g_done;        // finalize ticket
__device__ unsigned g_bar_count;   // grid barrier
__device__ unsigned g_bar_gen;     // grid barrier generation (monotonic, ok to persist)

__global__ void __launch_bounds__(NTHR, 2)
cox_persistent_kernel(const float* __restrict__ pred,
                      const int*   __restrict__ dur,
                      const int*   __restrict__ ev,
                      float* __restrict__ out,
                      int n)
{
    __shared__ float    sS[HSZ];          // hist -> scan -> logR LUT
    __shared__ float    rA[NWRP], rB[NWRP], rC[NWRP], rD[NWRP];
    __shared__ unsigned rN[NWRP];
    __shared__ unsigned sIsLast;

    const int t    = threadIdx.x;
    const int lane = t & 31, wid = t >> 5;
    const int nv   = n >> 2;
    const int stride = NBLK * NTHR;

    for (int i = t; i < HSZ; i += NTHR) sS[i] = 0.f;
    __syncthreads();

    // ================= PHASE 1: exp histogram (pred + dur only) =================
    {
        const float4* p4 = (const float4*)pred;
        const int4*   d4 = (const int4*)dur;
        for (int i = blockIdx.x * NTHR + t; i < nv; i += stride) {
            float4 y = p4[i];
            int4   d = d4[i];
            #pragma unroll
            for (int k = 0; k < 4; k++) {
                float x = fminf(fmaxf((&y.x)[k], -20.f), 20.f);
                atomicAdd(&sS[(&d.x)[k] & (HSZ - 1)], __expf(x));
            }
        }
        for (int i = (nv << 2) + blockIdx.x * NTHR + t; i < n; i += stride) {
            float x = fminf(fmaxf(pred[i], -20.f), 20.f);
            atomicAdd(&sS[dur[i] & (HSZ - 1)], __expf(x));
        }
    }
    __syncthreads();
    for (int i = t; i < MAXD; i += NTHR) {
        float s = sS[i];
        if (s != 0.f) atomicAdd(&g_S[i], s);
    }

    // ================= GRID SYNC =================
    __threadfence();
    __syncthreads();
    if (t == 0) {
        unsigned gen = atomicOr(&g_bar_gen, 0u);
        unsigned a   = atomicAdd(&g_bar_count, 1u);
        if (a == (unsigned)(NBLK - 1)) {
            atomicExch(&g_bar_count, 0u);
            __threadfence();
            atomicExch(&g_bar_gen, gen + 1u);
        } else {
            while (atomicOr(&g_bar_gen, 0u) == gen) { }
        }
    }
    __syncthreads();

    // ============ PHASE 1.5: every block builds the logR LUT locally ============
    {
        float s = (t < MAXD) ? __ldcg(&g_S[t]) : 0.f;
        sS[t] = s;
        __syncthreads();
        // Hillis-Steele inclusive suffix scan: sS[t] = sum_{j>=t} S[j]
        #pragma unroll
        for (int off = 1; off < HSZ; off <<= 1) {
            float v = (t + off < HSZ) ? sS[t + off] : 0.f;
            __syncthreads();
            sS[t] += v;
            __syncthreads();
        }
        float lg = logf(fmaxf(sS[t], 1e-12f));
        __syncthreads();
        sS[t] = lg;                  // LUT: sS[d] = log R(d)
        __syncthreads();
    }

    // ================= PHASE 2: gather (pred/dur from L2, ev) =================
    float slr_e = 0.f, slr_all = 0.f, sey = 0.f, sy = 0.f;
    unsigned nev = 0u;
    {
        const float4* p4 = (const float4*)pred;
        const int4*   d4 = (const int4*)dur;
        const int4*   e4 = (const int4*)ev;
        for (int i = blockIdx.x * NTHR + t; i < nv; i += stride) {
            float4 y = p4[i];
            int4   d = d4[i];
            int4   e = e4[i];
            #pragma unroll
            for (int k = 0; k < 4; k++) {
                float yy = (&y.x)[k];
                float lg = sS[(&d.x)[k] & (HSZ - 1)];
                float ef = (float)(&e.x)[k];
                slr_all += lg;
                sy      += yy;
                slr_e   += ef * lg;
                sey     += ef * yy;
                nev     += (unsigned)(&e.x)[k];
            }
        }
        for (int i = (nv << 2) + blockIdx.x * NTHR + t; i < n; i += stride) {
            float yy = pred[i];
            float lg = sS[dur[i] & (HSZ - 1)];
            int   ec = ev[i];
            float ef = (float)ec;
            slr_all += lg;  sy += yy;
            slr_e += ef * lg;  sey += ef * yy;  nev += (unsigned)ec;
        }
    }

    // block reduce 4 floats + 1 uint
    #pragma unroll
    for (int o = 16; o; o >>= 1) {
        slr_e   += __shfl_down_sync(0xffffffffu, slr_e,   o);
        slr_all += __shfl_down_sync(0xffffffffu, slr_all, o);
        sey     += __shfl_down_sync(0xffffffffu, sey,     o);
        sy      += __shfl_down_sync(0xffffffffu, sy,      o);
        nev     += __shfl_down_sync(0xffffffffu, nev,     o);
    }
    if (lane == 0) { rA[wid] = slr_e; rB[wid] = slr_all; rC[wid] = sey; rD[wid] = sy; rN[wid] = nev; }
    __syncthreads();
    if (t == 0) {
        float a = 0.f, b = 0.f, c = 0.f, d = 0.f; unsigned m = 0u;
        #pragma unroll
        for (int w = 0; w < NWRP; w++) { a += rA[w]; b += rB[w]; c += rC[w]; d += rD[w]; m += rN[w]; }
        atomicAdd(&g_slr_e, a);
        atomicAdd(&g_slr_all, b);
        atomicAdd(&g_sey, c);
        atomicAdd(&g_sy, d);
        atomicAdd(&g_nev, m);
    }

    // ================= FINALIZE (last block) =================
    __threadfence();
    __syncthreads();
    if (t == 0) {
        unsigned ticket = atomicAdd(&g_done, 1u);
        sIsLast = (ticket == (unsigned)(NBLK - 1)) ? 1u : 0u;
    }
    __syncthreads();
    if (!sIsLast) return;

    if (t == 0) {
        unsigned nev_tot = __ldcg(&g_nev);
        float total_ll, n_events;
        if (nev_tot > 0u) {
            total_ll = __ldcg(&g_sey) - __ldcg(&g_slr_e);
            n_events = fmaxf((float)nev_tot, 1.f);
        } else {
            // reference corner: e.sum()==0 -> e := 1e-8 everywhere
            total_ll = 1e-8f * (__ldcg(&g_sy) - __ldcg(&g_slr_all));
            n_events = fmaxf(1e-8f * (float)n, 1.f);
        }
        out[0] = -total_ll / n_events;
    }

    // re-zero globals for next graph replay
    for (int i = t; i < MAXD; i += NTHR) g_S[i] = 0.f;
    if (t == 0) {
        g_slr_e = 0.f; g_slr_all = 0.f; g_sey = 0.f; g_sy = 0.f;
        g_nev = 0u; g_done = 0u;
    }
}

extern "C" void kernel_launch(void* const* d_in, const int* in_sizes, int n_in,
                              void* d_out, int out_size)
{
    const float* pred = (const float*)d_in[0];
    const int*   dur  = (const int*)d_in[1];
    const int*   ev   = (const int*)d_in[2];
    int n = in_sizes[0];

    cox_persistent_kernel<<<NBLK, NTHR>>>(pred, dur, ev, (float*)d_out, n);
}

// round 7
// speedup vs baseline: 1.4043x; 1.1468x over previous
#include <cuda_runtime.h>

#define MAXD 365
#define HSZ  512          // padded hist/LUT, mask 511 (clamp-free, crash-proof)
#define NTHR 512
#define NBLK 444          // 3 blocks/SM * 148 SMs
#define NWRP (NTHR / 32)

__device__ float    g_S[MAXD];      // sum exp(clip(y)) per bucket
__device__ unsigned g_M[MAXD];      // event count per bucket
__device__ float    g_sey;          // sum e_i * y_i
__device__ float    g_sy;           // sum y_i (no-events corner)
__device__ unsigned g_done;         // finalize ticket

__global__ void __launch_bounds__(NTHR, 3)
cox_onepass_kernel(const float* __restrict__ pred,
                   const int*   __restrict__ dur,
                   const int*   __restrict__ ev,
                   float* __restrict__ out,
                   int n)
{
    __shared__ float    sS[HSZ];     // hist -> scan array -> logR LUT (finalize)
    __shared__ unsigned sMh[HSZ];    // event hist -> nev reduce (finalize)
    __shared__ float    redF[HSZ];   // finalize reduction scratch
    __shared__ float    wA[NWRP], wB[NWRP];
    __shared__ unsigned sIsLast;

    const int t    = threadIdx.x;
    const int lane = t & 31, wid = t >> 5;
    const int nv   = n >> 2;
    const int stride = NBLK * NTHR;

    for (int i = t; i < HSZ; i += NTHR) { sS[i] = 0.f; sMh[i] = 0u; }
    __syncthreads();

    float sey = 0.f, sy = 0.f;

    // ============ single pass: histogram S, histogram M, reduce sey/sy ============
    {
        const float4* p4 = (const float4*)pred;
        const int4*   d4 = (const int4*)dur;
        const int4*   e4 = (const int4*)ev;
        for (int i = blockIdx.x * NTHR + t; i < nv; i += stride) {
            float4 y = p4[i];
            int4   d = d4[i];
            int4   e = e4[i];
            #pragma unroll
            for (int k = 0; k < 4; k++) {
                float yy = (&y.x)[k];
                int   dd = (&d.x)[k] & (HSZ - 1);
                int   ec = (&e.x)[k];
                float x  = fminf(fmaxf(yy, -20.f), 20.f);
                atomicAdd(&sS[dd], __expf(x));
                if (ec) {
                    atomicAdd(&sMh[dd], 1u);
                    sey += yy;
                }
                sy += yy;
            }
        }
        for (int i = (nv << 2) + blockIdx.x * NTHR + t; i < n; i += stride) {
            float yy = pred[i];
            int   dd = dur[i] & (HSZ - 1);
            int   ec = ev[i];
            float x  = fminf(fmaxf(yy, -20.f), 20.f);
            atomicAdd(&sS[dd], __expf(x));
            if (ec) { atomicAdd(&sMh[dd], 1u); sey += yy; }
            sy += yy;
        }
    }

    // block-reduce sey, sy -> global
    #pragma unroll
    for (int o = 16; o; o >>= 1) {
        sey += __shfl_down_sync(0xffffffffu, sey, o);
        sy  += __shfl_down_sync(0xffffffffu, sy,  o);
    }
    if (lane == 0) { wA[wid] = sey; wB[wid] = sy; }
    __syncthreads();
    if (t == 0) {
        float a = 0.f, b = 0.f;
        #pragma unroll
        for (int w = 0; w < NWRP; w++) { a += wA[w]; b += wB[w]; }
        atomicAdd(&g_sey, a);
        atomicAdd(&g_sy,  b);
    }

    // flush histograms (skip empties)
    for (int i = t; i < MAXD; i += NTHR) {
        float s = sS[i];
        if (s != 0.f) atomicAdd(&g_S[i], s);
        unsigned m = sMh[i];
        if (m)        atomicAdd(&g_M[i], m);
    }

    // ================= last-block finalize =================
    __threadfence();
    if (t == 0) {
        unsigned ticket = atomicAdd(&g_done, 1u);
        sIsLast = (ticket == (unsigned)(NBLK - 1)) ? 1u : 0u;
    }
    __syncthreads();
    if (!sIsLast) return;

    float    s = (t < MAXD) ? __ldcg(&g_S[t]) : 0.f;
    unsigned m = (t < MAXD) ? __ldcg(&g_M[t]) : 0u;
    __syncthreads();
    sS[t] = s;
    __syncthreads();

    // Hillis-Steele inclusive suffix scan: sS[t] = sum_{j>=t} S[j]
    #pragma unroll
    for (int off = 1; off < HSZ; off <<= 1) {
        float v = (t + off < HSZ) ? sS[t + off] : 0.f;
        __syncthreads();
        sS[t] += v;
        __syncthreads();
    }

    float lg = logf(fmaxf(sS[t], 1e-12f));
    __syncthreads();
    sS[t]   = (t < MAXD) ? lg : 0.f;     // logR LUT (for dead corner)
    redF[t] = (float)m * ((t < MAXD) ? lg : 0.f);
    sMh[t]  = m;
    __syncthreads();

    #pragma unroll
    for (int off = HSZ / 2; off; off >>= 1) {
        if (t < off) {
            redF[t] += redF[t + off];
            sMh[t]  += sMh[t + off];
        }
        __syncthreads();
    }

    unsigned nev = sMh[0];

    if (nev > 0u) {
        if (t == 0) {
            float total_ll = __ldcg(&g_sey) - redF[0];
            out[0] = -total_ll / fmaxf((float)nev, 1.f);
        }
    } else {
        // dead-in-practice corner: e.sum()==0 -> e := 1e-8 everywhere.
        // Need sum_i logR[dur_i]: rescan durations with this one block.
        float slr = 0.f;
        for (int i = t; i < n; i += NTHR)
            slr += sS[dur[i] & (HSZ - 1)];
        #pragma unroll
        for (int o = 16; o; o >>= 1)
            slr += __shfl_down_sync(0xffffffffu, slr, o);
        if (lane == 0) wA[wid] = slr;
        __syncthreads();
        if (t == 0) {
            float tot = 0.f;
            #pragma unroll
            for (int w = 0; w < NWRP; w++) tot += wA[w];
            float total_ll = 1e-8f * (__ldcg(&g_sy) - tot);
            float n_events = fmaxf(1e-8f * (float)n, 1.f);
            out[0] = -total_ll / n_events;
        }
    }

    // re-zero globals for next graph replay
    __syncthreads();
    for (int i = t; i < MAXD; i += NTHR) { g_S[i] = 0.f; g_M[i] = 0u; }
    if (t == 0) { g_sey = 0.f; g_sy = 0.f; g_done = 0u; }
}

extern "C" void kernel_launch(void* const* d_in, const int* in_sizes, int n_in,
                              void* d_out, int out_size)
{
    const float* pred = (const float*)d_in[0];
    const int*   dur  = (const int*)d_in[1];
    const int*   ev   = (const int*)d_in[2];
    int n = in_sizes[0];

    cox_onepass_kernel<<<NBLK, NTHR>>>(pred, dur, ev, (float*)d_out, n);
}

// round 8
// speedup vs baseline: 1.5226x; 1.0842x over previous
#include <cuda_runtime.h>

#define MAXD 365
#define NREP 8            // histogram replicas (warp>>1 selects)
#define RSTR 369          // replica stride (mod 32 = 17: decorrelates banks)
#define NTHR 512
#define NBLK 444          // 3 blocks/SM * 148 SMs
#define NWRP (NTHR / 32)

__device__ float    g_S[MAXD];      // sum exp(clip(y)) per bucket
__device__ unsigned g_M[MAXD];      // event count per bucket
__device__ float    g_sey;          // sum e_i * y_i
__device__ unsigned g_done;         // finalize ticket

__global__ void __launch_bounds__(NTHR, 3)
cox_rep_kernel(const float* __restrict__ pred,
               const int*   __restrict__ dur,
               const int*   __restrict__ ev,
               float* __restrict__ out,
               int n)
{
    __shared__ float    sS[NREP * RSTR];    // replicated exp hist (reused in finalize)
    __shared__ unsigned sMh[NREP * RSTR];   // replicated event hist
    __shared__ float    wA[NWRP];
    __shared__ unsigned sIsLast;

    const int t    = threadIdx.x;
    const int lane = t & 31, wid = t >> 5;
    const int rep  = (wid >> 1) & (NREP - 1);
    const int rb   = rep * RSTR;
    const int nv   = n >> 2;
    const int stride = NBLK * NTHR;

    for (int i = t; i < NREP * RSTR; i += NTHR) { sS[i] = 0.f; sMh[i] = 0u; }
    __syncthreads();

    float sey = 0.f;

    // ============ single pass: replicated histograms + sey reduce ============
    {
        const float4* p4 = (const float4*)pred;
        const int4*   d4 = (const int4*)dur;
        const int4*   e4 = (const int4*)ev;
        for (int i = blockIdx.x * NTHR + t; i < nv; i += stride) {
            float4 y = p4[i];
            int4   d = d4[i];
            int4   e = e4[i];
            #pragma unroll
            for (int k = 0; k < 4; k++) {
                float yy = (&y.x)[k];
                int   dd = (&d.x)[k];
                dd = (dd < 0) ? 0 : ((dd >= MAXD) ? MAXD - 1 : dd);
                int   ec = (&e.x)[k];
                float x  = fminf(fmaxf(yy, -20.f), 20.f);
                atomicAdd(&sS[rb + dd], __expf(x));
                if (ec) {
                    atomicAdd(&sMh[rb + dd], 1u);
                    sey += yy;
                }
            }
        }
        for (int i = (nv << 2) + blockIdx.x * NTHR + t; i < n; i += stride) {
            float yy = pred[i];
            int   dd = dur[i];
            dd = (dd < 0) ? 0 : ((dd >= MAXD) ? MAXD - 1 : dd);
            int   ec = ev[i];
            float x  = fminf(fmaxf(yy, -20.f), 20.f);
            atomicAdd(&sS[rb + dd], __expf(x));
            if (ec) { atomicAdd(&sMh[rb + dd], 1u); sey += yy; }
        }
    }

    // block-reduce sey -> global
    #pragma unroll
    for (int o = 16; o; o >>= 1)
        sey += __shfl_down_sync(0xffffffffu, sey, o);
    if (lane == 0) wA[wid] = sey;
    __syncthreads();
    if (t == 0) {
        float a = 0.f;
        #pragma unroll
        for (int w = 0; w < NWRP; w++) a += wA[w];
        atomicAdd(&g_sey, a);
    }

    // flush: sum replicas, then one global atomic per non-empty bucket
    for (int i = t; i < MAXD; i += NTHR) {
        float    s = 0.f;
        unsigned m = 0u;
        #pragma unroll
        for (int r = 0; r < NREP; r++) {
            s += sS[r * RSTR + i];
            m += sMh[r * RSTR + i];
        }
        if (s != 0.f) atomicAdd(&g_S[i], s);
        if (m)        atomicAdd(&g_M[i], m);
    }

    // ================= last-block finalize =================
    __threadfence();
    if (t == 0) {
        unsigned ticket = atomicAdd(&g_done, 1u);
        sIsLast = (ticket == (unsigned)(NBLK - 1)) ? 1u : 0u;
    }
    __syncthreads();
    if (!sIsLast) return;

    // shared reuse: scan[0..511] = sS, redF[0..511] = sS+1024, counts = sMh
    float*    scan = sS;
    float*    redF = sS + 1024;
    unsigned* redN = sMh;

    float    s = (t < MAXD) ? __ldcg(&g_S[t]) : 0.f;
    unsigned m = (t < MAXD) ? __ldcg(&g_M[t]) : 0u;
    __syncthreads();
    scan[t] = s;
    __syncthreads();

    // Hillis-Steele inclusive suffix scan: scan[t] = sum_{j>=t} S[j]
    #pragma unroll
    for (int off = 1; off < NTHR; off <<= 1) {
        float v = (t + off < NTHR) ? scan[t + off] : 0.f;
        __syncthreads();
        scan[t] += v;
        __syncthreads();
    }

    float lg = logf(fmaxf(scan[t], 1e-12f));
    __syncthreads();
    scan[t] = (t < MAXD) ? lg : 0.f;        // logR LUT (dead corner)
    redF[t] = (float)m * ((t < MAXD) ? lg : 0.f);
    redN[t] = m;
    __syncthreads();

    #pragma unroll
    for (int off = NTHR / 2; off; off >>= 1) {
        if (t < off) {
            redF[t] += redF[t + off];
            redN[t] += redN[t + off];
        }
        __syncthreads();
    }

    unsigned nev = redN[0];

    if (nev > 0u) {
        if (t == 0) {
            float total_ll = __ldcg(&g_sey) - redF[0];
            out[0] = -total_ll / fmaxf((float)nev, 1.f);
        }
    } else {
        // dead-in-practice corner: e.sum()==0 -> e := 1e-8 everywhere.
        // Need sum_i logR[dur_i] and sum_i y_i: rescan with this one block.
        float slr = 0.f, syl = 0.f;
        for (int i = t; i < n; i += NTHR) {
            int dd = dur[i];
            dd = (dd < 0) ? 0 : ((dd >= MAXD) ? MAXD - 1 : dd);
            slr += scan[dd];
            syl += pred[i];
        }
        #pragma unroll
        for (int o = 16; o; o >>= 1) {
            slr += __shfl_down_sync(0xffffffffu, slr, o);
            syl += __shfl_down_sync(0xffffffffu, syl, o);
        }
        if (lane == 0) { wA[wid] = slr; redF[wid] = syl; }
        __syncthreads();
        if (t == 0) {
            float tot = 0.f, sy = 0.f;
            #pragma unroll
            for (int w = 0; w < NWRP; w++) { tot += wA[w]; sy += redF[w]; }
            float total_ll = 1e-8f * (sy - tot);
            float n_events = fmaxf(1e-8f * (float)n, 1.f);
            out[0] = -total_ll / n_events;
        }
    }

    // re-zero globals for next graph replay
    __syncthreads();
    for (int i = t; i < MAXD; i += NTHR) { g_S[i] = 0.f; g_M[i] = 0u; }
    if (t == 0) { g_sey = 0.f; g_done = 0u; }
}

extern "C" void kernel_launch(void* const* d_in, const int* in_sizes, int n_in,
                              void* d_out, int out_size)
{
    const float* pred = (const float*)d_in[0];
    const int*   dur  = (const int*)d_in[1];
    const int*   ev   = (const int*)d_in[2];
    int n = in_sizes[0];

    cox_rep_kernel<<<NBLK, NTHR>>>(pred, dur, ev, (float*)d_out, n);
}